// round 7
// baseline (speedup 1.0000x reference)
#include <cuda_runtime.h>
#include <cuda_bf16.h>
#include <cstdint>
#include <math.h>

// Problem constants
#define BB 2048
#define DD 4096
#define PP 64
#define EE 8
#define KK 64
#define TWO_C 128

#define WROW 72          // padded row stride in bf16 (144 B): conflict-free ldmatrix
#define WROWB 144

#define RBLK (BB / 2)    // router blocks: 2 b's per block, 4 warps per b

// inter-kernel scratch
__device__ float g_select[BB * EE];
__device__ float g_gate[BB];
__device__ int   g_index[BB];
__device__ int   g_order[BB];         // b's sorted by expert
__device__ unsigned int g_ticket;     // router completion ticket (self-resetting)

// ---------------- helpers ----------------
__device__ __forceinline__ uint32_t smem_u32(const void* p) {
    uint32_t a;
    asm("{ .reg .u64 t; cvta.to.shared.u64 t, %1; cvt.u32.u64 %0, t; }" : "=r"(a) : "l"(p));
    return a;
}

__device__ __forceinline__ void ldsm_x4(uint32_t& r0, uint32_t& r1, uint32_t& r2, uint32_t& r3,
                                        uint32_t addr) {
    asm volatile("ldmatrix.sync.aligned.m8n8.x4.shared.b16 {%0,%1,%2,%3}, [%4];"
                 : "=r"(r0), "=r"(r1), "=r"(r2), "=r"(r3) : "r"(addr));
}

__device__ __forceinline__ void mma_bf16(float* d, const uint32_t* a, uint32_t b0, uint32_t b1) {
    asm volatile(
        "mma.sync.aligned.m16n8k16.row.col.f32.bf16.bf16.f32 "
        "{%0,%1,%2,%3}, {%4,%5,%6,%7}, {%8,%9}, {%0,%1,%2,%3};"
        : "+f"(d[0]), "+f"(d[1]), "+f"(d[2]), "+f"(d[3])
        : "r"(a[0]), "r"(a[1]), "r"(a[2]), "r"(a[3]), "r"(b0), "r"(b1));
}

__device__ __forceinline__ uint32_t pack_bf16x2(float lo, float hi) {
    __nv_bfloat162 h = __float22bfloat162_rn(make_float2(lo, hi));
    return *(uint32_t*)&h;
}

__device__ __forceinline__ void cp_async16(uint32_t smem_addr, const void* gmem) {
    asm volatile("cp.async.cg.shared.global [%0], [%1], 16;" :: "r"(smem_addr), "l"(gmem));
}

// ---------------------------------------------------------------------------
// K1: router (+ fused compaction & loss in the last-finishing block).
// 1024 blocks x 256 threads; 2 b's per block, 4 warps per b (8 LDG.128 each).
// ---------------------------------------------------------------------------
__global__ __launch_bounds__(256) void router_kernel(
    const float* __restrict__ x,
    const float* __restrict__ rw,
    float* __restrict__ out,
    int full)
{
    __shared__ float4 sacc[8][16];
    __shared__ int    s_last;
    // compact-phase smem
    __shared__ int   hist[EE];
    __shared__ int   ofs[EE];
    __shared__ float esum[8][EE];

    const int t = threadIdx.x;
    const int wid = t >> 5, lid = t & 31;
    const int wq = wid & 3;                    // quarter of x[b]
    const int jb = wid >> 2;                   // local b (0..1)
    const int b = blockIdx.x * 2 + jb;

    const float4* xb4 = (const float4*)(x + (size_t)b * DD);
    float4 acc = make_float4(0.f, 0.f, 0.f, 0.f);
    #pragma unroll
    for (int i = 0; i < 8; i++) {
        float4 v = xb4[lid + (((wq << 3) + i) << 5)];
        acc.x += v.x; acc.y += v.y; acc.z += v.z; acc.w += v.w;
    }
    acc.x += __shfl_xor_sync(0xffffffffu, acc.x, 16);
    acc.y += __shfl_xor_sync(0xffffffffu, acc.y, 16);
    acc.z += __shfl_xor_sync(0xffffffffu, acc.z, 16);
    acc.w += __shfl_xor_sync(0xffffffffu, acc.w, 16);
    if (lid < 16) sacc[wid][lid] = acc;
    __syncthreads();

    if (wq == 0) {
        #pragma unroll
        for (int q = 1; q < 4; q++) {
            float4 o = sacc[wid + q][lid & 15];
            acc.x += o.x; acc.y += o.y; acc.z += o.z; acc.w += o.w;
        }
        // acc now holds xs for k-group (lid&15), duplicated across half-warps
        const float4* rw4 = (const float4*)rw;
        float sel[EE];
        #pragma unroll
        for (int e = 0; e < EE; e++) {
            float4 w = rw4[e * 16 + (lid & 15)];
            float p = acc.x * w.x + acc.y * w.y + acc.z * w.z + acc.w * w.w;
            p += __shfl_xor_sync(0xffffffffu, p, 8);
            p += __shfl_xor_sync(0xffffffffu, p, 4);
            p += __shfl_xor_sync(0xffffffffu, p, 2);
            p += __shfl_xor_sync(0xffffffffu, p, 1);
            sel[e] = p;
        }
        float g = sel[0]; int idx = 0;
        #pragma unroll
        for (int e = 1; e < EE; e++) { if (sel[e] > g) { g = sel[e]; idx = e; } }

        if (lid == 0) {
            g_index[b] = idx;
            g_gate[b]  = g;
            float4* s4 = (float4*)(g_select + b * EE);
            s4[0] = make_float4(sel[0], sel[1], sel[2], sel[3]);
            s4[1] = make_float4(sel[4], sel[5], sel[6], sel[7]);
        }
        if (full && lid < EE)
            out[BB * 2 + b * EE + lid] = (lid == idx && g != 0.f) ? 1.f : 0.f;
    }
    __syncthreads();

    // ---- completion ticket; last block performs compaction + loss
    if (t == 0) {
        __threadfence();
        unsigned int tk = atomicAdd(&g_ticket, 1u);
        s_last = (tk == RBLK - 1) ? 1 : 0;
    }
    __syncthreads();
    if (!s_last) return;
    __threadfence();                            // acquire all blocks' writes

    if (t < EE) hist[t] = 0;
    __syncthreads();

    int idx8[8];
    #pragma unroll
    for (int i = 0; i < 8; i++) {
        idx8[i] = g_index[t + (i << 8)];
        atomicAdd(&hist[idx8[i]], 1);
    }
    __syncthreads();

    if (t == 0) {
        int run = 0;
        #pragma unroll
        for (int e = 0; e < EE; e++) { ofs[e] = run; run += hist[e]; }
    }
    __syncthreads();

    #pragma unroll
    for (int i = 0; i < 8; i++) {
        int pos = atomicAdd(&ofs[idx8[i]], 1);
        g_order[pos] = t + (i << 8);
    }

    // loss: S_e = sum_b select[b,e]; loss = E/B^2 * sum_e S_e*cnt_e
    float my[EE];
    #pragma unroll
    for (int e = 0; e < EE; e++) my[e] = 0.f;
    #pragma unroll
    for (int i = 0; i < 8; i++) {
        const float4* s4 = (const float4*)(g_select + (t + (i << 8)) * EE);
        float4 v0 = s4[0], v1 = s4[1];
        my[0] += v0.x; my[1] += v0.y; my[2] += v0.z; my[3] += v0.w;
        my[4] += v1.x; my[5] += v1.y; my[6] += v1.z; my[7] += v1.w;
    }
    #pragma unroll
    for (int o = 16; o > 0; o >>= 1)
        #pragma unroll
        for (int e = 0; e < EE; e++)
            my[e] += __shfl_xor_sync(0xffffffffu, my[e], o);
    if (lid == 0) {
        #pragma unroll
        for (int e = 0; e < EE; e++) esum[wid][e] = my[e];
    }
    __syncthreads();

    if (t == 0) {
        if (full) {
            float L = 0.f;
            #pragma unroll
            for (int e = 0; e < EE; e++) {
                float S = 0.f;
                #pragma unroll
                for (int w = 0; w < 8; w++) S += esum[w][e];
                L += S * (float)hist[e];
            }
            out[BB * 2 + BB * EE] = L * (float)EE / ((float)BB * (float)BB);
        }
        atomicExch(&g_ticket, 0u);              // reset for next graph replay
    }
}

// ---------------------------------------------------------------------------
// K2: expert GEMMs. 1024 blocks x 2 tasks; cp.async prefetch of task1's x.
// ---------------------------------------------------------------------------
__global__ __launch_bounds__(256, 3) void expert_kernel(
    const float* __restrict__ x,
    const float* __restrict__ ew,
    const float* __restrict__ eb,
    float* __restrict__ out)
{
    __shared__ __align__(16) __nv_bfloat16 asm_w[TWO_C * WROW];  // A: weights [c][k]
    __shared__ __align__(16) __nv_bfloat16 bsm_x[PP * WROW];     // B: x patches [p][k]
    __shared__ __align__(16) float xst[PP * KK];                 // fp32 stage for task1 x
    __shared__ float bias_s[TWO_C];
    __shared__ float wred[8];

    const int t = threadIdx.x;
    const int wid = t >> 5, lid = t & 31;
    const int cw = wid & 3;
    const int pw = wid >> 2;
    const uint32_t Abase = smem_u32(asm_w);
    const uint32_t Bbase = smem_u32(bsm_x);
    const uint32_t a_addr = Abase + (uint32_t)(((cw << 5) + (lid & 15)) * WROWB + ((lid >> 4) << 4));
    const uint32_t b_addr = Bbase + (uint32_t)(((pw << 5) + (lid & 7) + ((lid >> 4) << 3)) * WROWB
                                               + (((lid >> 3) & 1) << 4));
    const int k8 = (t & 7) << 3;
    const int pg = t >> 3;

    const int b0 = __ldg(&g_order[blockIdx.x * 2 + 0]);
    const int b1 = __ldg(&g_order[blockIdx.x * 2 + 1]);
    const int e0 = __ldg(&g_index[b0]);
    const int e1 = __ldg(&g_index[b1]);

    // prefetch task1 x into fp32 smem stage (64B per thread), overlaps everything below
    {
        const float* src = x + (size_t)b1 * DD + t * 16;
        uint32_t dst = smem_u32(xst) + (uint32_t)t * 64;
        #pragma unroll
        for (int i = 0; i < 4; i++)
            cp_async16(dst + i * 16, src + i * 4);
        asm volatile("cp.async.commit_group;" ::: "memory");
    }

    // stage weights(e0) fp32->bf16
    {
        const float4* src = (const float4*)(ew + (size_t)e0 * (TWO_C * KK));
        #pragma unroll
        for (int i = 0; i < 8; i++) {
            int idx4 = (i << 8) + t;
            float4 v = src[idx4];
            uint2 pk;
            pk.x = pack_bf16x2(v.x, v.y);
            pk.y = pack_bf16x2(v.z, v.w);
            *(uint2*)&asm_w[(idx4 >> 4) * WROW + ((idx4 & 15) << 2)] = pk;
        }
        if (t < TWO_C) bias_s[t] = eb[e0 * TWO_C + t];
    }
    // stage x(b0) fp32->bf16 directly
    {
        const float* xb = x + (size_t)b0 * DD;
        #pragma unroll
        for (int q = 0; q < 2; q++) {
            const int p = pg + (q << 5);
            const float4* xp = (const float4*)(xb + p * KK + k8);
            float4 v0 = xp[0], v1 = xp[1];
            uint4 pk;
            pk.x = pack_bf16x2(v0.x, v0.y);
            pk.y = pack_bf16x2(v0.z, v0.w);
            pk.z = pack_bf16x2(v1.x, v1.y);
            pk.w = pack_bf16x2(v1.z, v1.w);
            *(uint4*)&bsm_x[p * WROW + k8] = pk;
        }
    }
    __syncthreads();

    #pragma unroll
    for (int it = 0; it < 2; it++) {
        const int b = (it == 0) ? b0 : b1;

        // ---- GEMM: warp grid 4c x 2p; warp tile 32c x 32p
        float accv[2][4][4];
        #pragma unroll
        for (int m = 0; m < 2; m++)
            #pragma unroll
            for (int n = 0; n < 4; n++)
                #pragma unroll
                for (int i = 0; i < 4; i++) accv[m][n][i] = 0.f;

        #pragma unroll
        for (int ks = 0; ks < 4; ks++) {
            uint32_t a0[4], a1[4];
            ldsm_x4(a0[0], a0[1], a0[2], a0[3], a_addr + ks * 32);
            ldsm_x4(a1[0], a1[1], a1[2], a1[3], a_addr + 16 * WROWB + ks * 32);
            #pragma unroll
            for (int j = 0; j < 2; j++) {
                uint32_t r0, r1, r2, r3;
                ldsm_x4(r0, r1, r2, r3, b_addr + j * (16 * WROWB) + ks * 32);
                mma_bf16(accv[0][2 * j],     a0, r0, r1);
                mma_bf16(accv[0][2 * j + 1], a0, r2, r3);
                mma_bf16(accv[1][2 * j],     a1, r0, r1);
                mma_bf16(accv[1][2 * j + 1], a1, r2, r3);
            }
        }

        // ---- epilogue: z = d + bias[c]; sum z^3
        float part = 0.f;
        #pragma unroll
        for (int m = 0; m < 2; m++) {
            const float bv1 = bias_s[(cw << 5) + (m << 4) + (lid >> 2)];
            const float bv2 = bias_s[(cw << 5) + (m << 4) + (lid >> 2) + 8];
            #pragma unroll
            for (int n = 0; n < 4; n++) {
                float z0 = accv[m][n][0] + bv1;
                float z1 = accv[m][n][1] + bv1;
                float z2 = accv[m][n][2] + bv2;
                float z3 = accv[m][n][3] + bv2;
                part += z0 * z0 * z0 + z1 * z1 * z1 + z2 * z2 * z2 + z3 * z3 * z3;
            }
        }
        #pragma unroll
        for (int o = 16; o > 0; o >>= 1)
            part += __shfl_xor_sync(0xffffffffu, part, o);
        if (lid == 0) wred[wid] = part;
        __syncthreads();                       // GEMM/ldsm done; safe to retile

        if (t == 0) {
            float v0 = wred[0] + wred[1] + wred[4] + wred[5];   // c in [0,64)
            float v1 = wred[2] + wred[3] + wred[6] + wred[7];   // c in [64,128)
            float gate = __ldg(&g_gate[b]);
            float a0v = gate * v0, a1v = gate * v1;
            float m  = fmaxf(a0v, a1v);
            float ee0 = expf(a0v - m), ee1 = expf(a1v - m);
            float inv = 1.f / (ee0 + ee1);
            out[b * 2 + 0] = ee0 * inv;
            out[b * 2 + 1] = ee1 * inv;
        }

        if (it == 0) {
            // make prefetched x(b1) visible, restage weights if expert changed
            asm volatile("cp.async.wait_group 0;" ::: "memory");
            __syncthreads();
            if (e1 != e0) {
                const float4* src = (const float4*)(ew + (size_t)e1 * (TWO_C * KK));
                #pragma unroll
                for (int i = 0; i < 8; i++) {
                    int idx4 = (i << 8) + t;
                    float4 v = src[idx4];
                    uint2 pk;
                    pk.x = pack_bf16x2(v.x, v.y);
                    pk.y = pack_bf16x2(v.z, v.w);
                    *(uint2*)&asm_w[(idx4 >> 4) * WROW + ((idx4 & 15) << 2)] = pk;
                }
                if (t < TWO_C) bias_s[t] = eb[e1 * TWO_C + t];
            }
            // convert staged fp32 x(b1) -> bf16 B tile
            #pragma unroll
            for (int q = 0; q < 2; q++) {
                const int p = pg + (q << 5);
                float4 v0 = *(const float4*)&xst[p * KK + k8];
                float4 v1 = *(const float4*)&xst[p * KK + k8 + 4];
                uint4 pk;
                pk.x = pack_bf16x2(v0.x, v0.y);
                pk.y = pack_bf16x2(v0.z, v0.w);
                pk.z = pack_bf16x2(v1.x, v1.y);
                pk.w = pack_bf16x2(v1.z, v1.w);
                *(uint4*)&bsm_x[p * WROW + k8] = pk;
            }
            __syncthreads();
        }
    }
}

// ---------------------------------------------------------------------------
extern "C" void kernel_launch(void* const* d_in, const int* in_sizes, int n_in,
                              void* d_out, int out_size)
{
    const float* x  = (const float*)d_in[0];
    const float* rw = (const float*)d_in[1];
    const float* ew = (const float*)d_in[2];
    const float* eb = (const float*)d_in[3];
    float* out = (float*)d_out;

    const int full = (out_size >= BB * 2 + BB * EE + 1) ? 1 : 0;

    router_kernel<<<RBLK, 256>>>(x, rw, out, full);
    expert_kernel<<<BB / 2, 256>>>(x, ew, eb, out);
}